// round 1
// baseline (speedup 1.0000x reference)
#include <cuda_runtime.h>
#include <math.h>

#define NN     100000
#define NITEM  80000
#define DD     128
#define DX     64
#define NE     800000
#define NB     4096

// ---------------- device scratch (no allocations allowed) ----------------
__device__ __align__(16) float g_x [(size_t)NN * DD];
__device__ __align__(16) float g_xw[(size_t)NN * DD];
__device__ __align__(16) float g_h [(size_t)NN * DD];   // gat accumulator, then h
__device__ int      g_deg[NN];
__device__ unsigned g_m[NN];
__device__ float    g_s[NN];
__device__ float    g_logits[NE];
__device__ float    g_expv[NE];

__device__ __forceinline__ float lrelu(float v) { return v > 0.f ? v : 0.01f * v; }

// monotonic float<->uint mapping for atomicMax on floats
__device__ __forceinline__ unsigned fflip(float f) {
    unsigned u = __float_as_uint(f);
    return u ^ ((u >> 31) ? 0xFFFFFFFFu : 0x80000000u);
}
__device__ __forceinline__ float funflip(unsigned u) {
    u ^= ((u >> 31) ? 0x80000000u : 0xFFFFFFFFu);
    return __uint_as_float(u);
}

// ---------------- init: zero accumulators / softmax state ----------------
__global__ void k_init() {
    int i = blockIdx.x * 256 + threadIdx.x;
    if (i < NN * DD) g_h[i] = 0.f;
    if (i < NN) { g_deg[i] = 0; g_m[i] = 0x007FFFFFu; /* fflip(-inf) */ g_s[i] = 0.f; }
}

// ---------------- x = l2norm(tanh(feat @ W.T + b)), split item/user ----------------
__global__ void __launch_bounds__(256) k_gemm_x(
    const float* __restrict__ feat, const float* __restrict__ ufeat,
    const float* __restrict__ Wm, const float* __restrict__ bm,
    const float* __restrict__ Wu, const float* __restrict__ bu)
{
    extern __shared__ float smx[];
    float* As = smx;            // 64 x 128
    float* Bs = smx + 64 * DD;  // 128 x 128 (transposed W: Bs[k][j] = W[j][k])
    const int row0b = blockIdx.x * 64;
    const bool user = row0b >= NITEM;
    const float* A    = user ? (ufeat + (size_t)(row0b - NITEM) * DD)
                             : (feat  + (size_t)row0b * DD);
    const float* W    = user ? Wu : Wm;
    const float* bias = user ? bu : bm;
    int rowlim = NN - row0b; if (rowlim > 64) rowlim = 64;
    const int tid = threadIdx.x;

    for (int i = tid; i < 64 * 32; i += 256) {
        int r = i >> 5, c4 = i & 31;
        float4 v = make_float4(0.f, 0.f, 0.f, 0.f);
        if (r < rowlim) v = __ldg((const float4*)A + r * 32 + c4);
        *(float4*)&As[r * DD + c4 * 4] = v;
    }
    for (int i = tid; i < 128 * 32; i += 256) {
        int j = i & 127, c4 = i >> 7;
        float4 v = __ldg((const float4*)W + j * 32 + c4);
        Bs[(c4 * 4 + 0) * DD + j] = v.x;
        Bs[(c4 * 4 + 1) * DD + j] = v.y;
        Bs[(c4 * 4 + 2) * DD + j] = v.z;
        Bs[(c4 * 4 + 3) * DD + j] = v.w;
    }
    __syncthreads();

    const int warp = tid >> 5, lane = tid & 31;
    const int r0 = warp * 8, c0 = lane * 4;
    float acc[8][4];
    #pragma unroll
    for (int r = 0; r < 8; r++) { acc[r][0] = acc[r][1] = acc[r][2] = acc[r][3] = 0.f; }

    #pragma unroll 1
    for (int k = 0; k < DD; k += 4) {
        float4 b0v = *(const float4*)&Bs[(k + 0) * DD + c0];
        float4 b1v = *(const float4*)&Bs[(k + 1) * DD + c0];
        float4 b2v = *(const float4*)&Bs[(k + 2) * DD + c0];
        float4 b3v = *(const float4*)&Bs[(k + 3) * DD + c0];
        #pragma unroll
        for (int r = 0; r < 8; r++) {
            float4 a = *(const float4*)&As[(r0 + r) * DD + k];
            acc[r][0] += a.x * b0v.x + a.y * b1v.x + a.z * b2v.x + a.w * b3v.x;
            acc[r][1] += a.x * b0v.y + a.y * b1v.y + a.z * b2v.y + a.w * b3v.y;
            acc[r][2] += a.x * b0v.z + a.y * b1v.z + a.z * b2v.z + a.w * b3v.z;
            acc[r][3] += a.x * b0v.w + a.y * b1v.w + a.z * b2v.w + a.w * b3v.w;
        }
    }

    float4 bb = __ldg((const float4*)bias + lane);
    #pragma unroll
    for (int r = 0; r < 8; r++) {
        int grow = row0b + r0 + r;
        float v0 = tanhf(acc[r][0] + bb.x);
        float v1 = tanhf(acc[r][1] + bb.y);
        float v2 = tanhf(acc[r][2] + bb.z);
        float v3 = tanhf(acc[r][3] + bb.w);
        float ss = v0 * v0 + v1 * v1 + v2 * v2 + v3 * v3;
        #pragma unroll
        for (int o = 16; o; o >>= 1) ss += __shfl_xor_sync(0xffffffffu, ss, o);
        float inv = 1.f / fmaxf(sqrtf(ss), 1e-12f);
        if (grow < NN)
            *(float4*)&g_x[(size_t)grow * DD + c0] =
                make_float4(v0 * inv, v1 * inv, v2 * inv, v3 * inv);
    }
}

// ---------------- xw = x @ W_gat (no transpose, no activation) ----------------
__global__ void __launch_bounds__(256) k_gemm_xw(const float* __restrict__ Wg)
{
    extern __shared__ float smx[];
    float* As = smx;
    float* Bs = smx + 64 * DD;
    const int row0b = blockIdx.x * 64;
    int rowlim = NN - row0b; if (rowlim > 64) rowlim = 64;
    const int tid = threadIdx.x;

    for (int i = tid; i < 64 * 32; i += 256) {
        int r = i >> 5, c4 = i & 31;
        float4 v = make_float4(0.f, 0.f, 0.f, 0.f);
        if (r < rowlim) v = *((const float4*)(g_x + (size_t)(row0b + r) * DD) + c4);
        *(float4*)&As[r * DD + c4 * 4] = v;
    }
    for (int i = tid; i < 128 * 32; i += 256) {
        int k = i >> 5, c4 = i & 31;
        float4 v = __ldg((const float4*)Wg + k * 32 + c4);
        *(float4*)&Bs[k * DD + c4 * 4] = v;
    }
    __syncthreads();

    const int warp = tid >> 5, lane = tid & 31;
    const int r0 = warp * 8, c0 = lane * 4;
    float acc[8][4];
    #pragma unroll
    for (int r = 0; r < 8; r++) { acc[r][0] = acc[r][1] = acc[r][2] = acc[r][3] = 0.f; }

    #pragma unroll 1
    for (int k = 0; k < DD; k += 4) {
        float4 b0v = *(const float4*)&Bs[(k + 0) * DD + c0];
        float4 b1v = *(const float4*)&Bs[(k + 1) * DD + c0];
        float4 b2v = *(const float4*)&Bs[(k + 2) * DD + c0];
        float4 b3v = *(const float4*)&Bs[(k + 3) * DD + c0];
        #pragma unroll
        for (int r = 0; r < 8; r++) {
            float4 a = *(const float4*)&As[(r0 + r) * DD + k];
            acc[r][0] += a.x * b0v.x + a.y * b1v.x + a.z * b2v.x + a.w * b3v.x;
            acc[r][1] += a.x * b0v.y + a.y * b1v.y + a.z * b2v.y + a.w * b3v.y;
            acc[r][2] += a.x * b0v.z + a.y * b1v.z + a.z * b2v.z + a.w * b3v.z;
            acc[r][3] += a.x * b0v.w + a.y * b1v.w + a.z * b2v.w + a.w * b3v.w;
        }
    }
    #pragma unroll
    for (int r = 0; r < 8; r++) {
        int grow = row0b + r0 + r;
        if (grow < NN)
            *(float4*)&g_xw[(size_t)grow * DD + c0] =
                make_float4(acc[r][0], acc[r][1], acc[r][2], acc[r][3]);
    }
}

// ---------------- out-degree of src ----------------
__global__ void k_deg(const int* __restrict__ ei) {
    int e = blockIdx.x * 256 + threadIdx.x;
    if (e < NE) atomicAdd(&g_deg[ei[e]], 1);
}

// ---------------- per-edge logits + segment max over dst (warp per edge) ----------------
__global__ void k_logits(const int* __restrict__ ei) {
    int gt = blockIdx.x * 256 + threadIdx.x;
    int e = gt >> 5, lane = gt & 31;
    if (e >= NE) return;
    int sj = __ldg(ei + e);
    int di = __ldg(ei + NE + e);
    float4 a = *((const float4*)(g_xw + (size_t)sj * DD) + lane);
    float4 b = *((const float4*)(g_xw + (size_t)di * DD) + lane);
    float p = a.x * b.x + a.y * b.y + a.z * b.z + a.w * b.w;
    #pragma unroll
    for (int o = 16; o; o >>= 1) p += __shfl_xor_sync(0xffffffffu, p, o);
    if (lane == 0) {
        float dinv = rsqrtf((float)g_deg[sj]);
        float gate = 1.f / (1.f + expf(-dinv * p));
        float lg = p * gate;
        g_logits[e] = lg;
        atomicMax(&g_m[di], fflip(lg));
    }
}

// ---------------- softmax denominators ----------------
__global__ void k_denom(const int* __restrict__ ei) {
    int e = blockIdx.x * 256 + threadIdx.x;
    if (e >= NE) return;
    int di = ei[NE + e];
    float mm = funflip(g_m[di]);
    float ev = expf(g_logits[e] - mm);
    g_expv[e] = ev;
    atomicAdd(&g_s[di], ev);
}

// ---------------- weighted scatter: acc[dst] += att * xw[src] ----------------
__global__ void k_scatter(const int* __restrict__ ei) {
    int gt = blockIdx.x * 256 + threadIdx.x;
    int e = gt >> 5, lane = gt & 31;
    if (e >= NE) return;
    int sj = __ldg(ei + e);
    int di = __ldg(ei + NE + e);
    float att = g_expv[e] / (g_s[di] + 1e-16f);
    float4 a = *((const float4*)(g_xw + (size_t)sj * DD) + lane);
    float4 v = make_float4(a.x * att, a.y * att, a.z * att, a.w * att);
    atomicAdd((float4*)(g_h + (size_t)di * DD) + lane, v);   // sm_90+ vector red
}

// ---------------- h = lrelu(l2norm(acc + b_gat)) in place ----------------
__global__ void k_finalize(const float* __restrict__ b_gat) {
    int gt = blockIdx.x * 256 + threadIdx.x;
    int w = gt >> 5, lane = gt & 31;
    if (w >= NN) return;
    float4 v = *((float4*)(g_h + (size_t)w * DD) + lane);
    float4 bb = __ldg((const float4*)b_gat + lane);
    v.x += bb.x; v.y += bb.y; v.z += bb.z; v.w += bb.w;
    float ss = v.x * v.x + v.y * v.y + v.z * v.z + v.w * v.w;
    #pragma unroll
    for (int o = 16; o; o >>= 1) ss += __shfl_xor_sync(0xffffffffu, ss, o);
    float inv = 1.f / fmaxf(sqrtf(ss), 1e-12f);
    v.x = lrelu(v.x * inv); v.y = lrelu(v.y * inv);
    v.z = lrelu(v.z * inv); v.w = lrelu(v.w * inv);
    *((float4*)(g_h + (size_t)w * DD) + lane) = v;
}

// ---------------- rep = lrelu(h@Wg1.T + bg1 + lrelu(x@Wl1.T + bl1) + id_emb) ----------------
__global__ void __launch_bounds__(256) k_rep(
    const float* __restrict__ Wl1, const float* __restrict__ bl1,
    const float* __restrict__ Wg1, const float* __restrict__ bg1,
    const float* __restrict__ id_emb, float* __restrict__ rep)
{
    extern __shared__ float smx[];
    float* Xs  = smx;                 // 64 x 128
    float* Hs  = smx + 8192;          // 64 x 128
    float* W1s = smx + 16384;         // 128 x 64 (transposed Wl1)
    float* Wgs = smx + 16384 + 8192;  // 128 x 64 (transposed Wg1)
    const int row0b = blockIdx.x * 64;
    int rowlim = NN - row0b; if (rowlim > 64) rowlim = 64;
    const int tid = threadIdx.x;

    for (int i = tid; i < 64 * 32; i += 256) {
        int r = i >> 5, c4 = i & 31;
        float4 vx = make_float4(0.f, 0.f, 0.f, 0.f), vh = vx;
        if (r < rowlim) {
            vx = *((const float4*)(g_x + (size_t)(row0b + r) * DD) + c4);
            vh = *((const float4*)(g_h + (size_t)(row0b + r) * DD) + c4);
        }
        *(float4*)&Xs[r * DD + c4 * 4] = vx;
        *(float4*)&Hs[r * DD + c4 * 4] = vh;
    }
    for (int i = tid; i < 64 * 32; i += 256) {
        int j = i & 63, c4 = i >> 6;
        float4 v1 = __ldg((const float4*)Wl1 + j * 32 + c4);
        float4 vg = __ldg((const float4*)Wg1 + j * 32 + c4);
        W1s[(c4 * 4 + 0) * DX + j] = v1.x; W1s[(c4 * 4 + 1) * DX + j] = v1.y;
        W1s[(c4 * 4 + 2) * DX + j] = v1.z; W1s[(c4 * 4 + 3) * DX + j] = v1.w;
        Wgs[(c4 * 4 + 0) * DX + j] = vg.x; Wgs[(c4 * 4 + 1) * DX + j] = vg.y;
        Wgs[(c4 * 4 + 2) * DX + j] = vg.z; Wgs[(c4 * 4 + 3) * DX + j] = vg.w;
    }
    __syncthreads();

    const int warp = tid >> 5, lane = tid & 31;
    const int r0 = warp * 8, c0 = lane * 2;
    float a1[8][2], a2[8][2];
    #pragma unroll
    for (int r = 0; r < 8; r++) { a1[r][0] = a1[r][1] = a2[r][0] = a2[r][1] = 0.f; }

    #pragma unroll 1
    for (int k = 0; k < DD; k += 4) {
        float2 w10 = *(const float2*)&W1s[(k + 0) * DX + c0];
        float2 w11 = *(const float2*)&W1s[(k + 1) * DX + c0];
        float2 w12 = *(const float2*)&W1s[(k + 2) * DX + c0];
        float2 w13 = *(const float2*)&W1s[(k + 3) * DX + c0];
        float2 wg0 = *(const float2*)&Wgs[(k + 0) * DX + c0];
        float2 wg1 = *(const float2*)&Wgs[(k + 1) * DX + c0];
        float2 wg2 = *(const float2*)&Wgs[(k + 2) * DX + c0];
        float2 wg3 = *(const float2*)&Wgs[(k + 3) * DX + c0];
        #pragma unroll
        for (int r = 0; r < 8; r++) {
            float4 ax = *(const float4*)&Xs[(r0 + r) * DD + k];
            float4 ah = *(const float4*)&Hs[(r0 + r) * DD + k];
            a1[r][0] += ax.x * w10.x + ax.y * w11.x + ax.z * w12.x + ax.w * w13.x;
            a1[r][1] += ax.x * w10.y + ax.y * w11.y + ax.z * w12.y + ax.w * w13.y;
            a2[r][0] += ah.x * wg0.x + ah.y * wg1.x + ah.z * wg2.x + ah.w * wg3.x;
            a2[r][1] += ah.x * wg0.y + ah.y * wg1.y + ah.z * wg2.y + ah.w * wg3.y;
        }
    }

    float2 bl = make_float2(__ldg(bl1 + c0), __ldg(bl1 + c0 + 1));
    float2 bg = make_float2(__ldg(bg1 + c0), __ldg(bg1 + c0 + 1));
    #pragma unroll
    for (int r = 0; r < 8; r++) {
        int grow = row0b + r0 + r;
        if (grow < NN) {
            float2 em = __ldg((const float2*)(id_emb + (size_t)grow * DX) + lane);
            float xh0 = lrelu(a1[r][0] + bl.x) + em.x;
            float xh1 = lrelu(a1[r][1] + bl.y) + em.y;
            float v0 = lrelu(a2[r][0] + bg.x + xh0);
            float v1 = lrelu(a2[r][1] + bg.y + xh1);
            *(float2*)&rep[(size_t)grow * DX + c0] = make_float2(v0, v1);
        }
    }
}

// ---------------- batch head (one warp per batch element) ----------------
__global__ void k_batch(const float* __restrict__ rep,
                        const int* __restrict__ un, const int* __restrict__ pit,
                        const int* __restrict__ nit,
                        const float* __restrict__ Wp1, const float* __restrict__ bp1,
                        const float* __restrict__ Wp2, const float* __restrict__ bp2,
                        float* __restrict__ out_pos, float* __restrict__ out_neg,
                        float* __restrict__ out_pred)
{
    int gt = blockIdx.x * 256 + threadIdx.x;
    int w = gt >> 5, lane = gt & 31;
    if (w >= NB) return;
    int iu = __ldg(un + w), ip = __ldg(pit + w), inn = __ldg(nit + w);
    float u0 = __ldg(rep + (size_t)iu * DX + lane), u1 = __ldg(rep + (size_t)iu * DX + 32 + lane);
    float p0 = __ldg(rep + (size_t)ip * DX + lane), p1 = __ldg(rep + (size_t)ip * DX + 32 + lane);
    float n0 = __ldg(rep + (size_t)inn * DX + lane), n1 = __ldg(rep + (size_t)inn * DX + 32 + lane);
    float ps = u0 * p0 + u1 * p1;
    float ns = u0 * n0 + u1 * n1;
    #pragma unroll
    for (int o = 16; o; o >>= 1) {
        ps += __shfl_xor_sync(0xffffffffu, ps, o);
        ns += __shfl_xor_sync(0xffffffffu, ns, o);
    }
    float h0 = __ldg(bp1 + lane), h1 = __ldg(bp1 + lane + 32);
    #pragma unroll 4
    for (int k = 0; k < 128; k++) {
        float srcv = (k < 32) ? u0 : (k < 64) ? u1 : (k < 96) ? p0 : p1;
        float v = __shfl_sync(0xffffffffu, srcv, k & 31);
        h0 += __ldg(Wp1 + lane * 128 + k) * v;
        h1 += __ldg(Wp1 + (lane + 32) * 128 + k) * v;
    }
    h0 = lrelu(h0); h1 = lrelu(h1);
    float pp = __ldg(Wp2 + lane) * h0 + __ldg(Wp2 + lane + 32) * h1;
    #pragma unroll
    for (int o = 16; o; o >>= 1) pp += __shfl_xor_sync(0xffffffffu, pp, o);
    if (lane == 0) {
        out_pos[w] = ps;
        out_neg[w] = ns;
        out_pred[w] = 1.f / (1.f + expf(-(pp + __ldg(bp2))));
    }
}

// ---------------- launch ----------------
extern "C" void kernel_launch(void* const* d_in, const int* in_sizes, int n_in,
                              void* d_out, int out_size)
{
    const float* feat   = (const float*)d_in[0];
    const float* ufeat  = (const float*)d_in[1];
    const float* Wm     = (const float*)d_in[2];
    const float* bm     = (const float*)d_in[3];
    const float* Wu     = (const float*)d_in[4];
    const float* bu     = (const float*)d_in[5];
    const float* Wgat   = (const float*)d_in[6];
    const float* bgat   = (const float*)d_in[7];
    const float* Wl1    = (const float*)d_in[8];
    const float* bl1    = (const float*)d_in[9];
    const float* Wg1    = (const float*)d_in[10];
    const float* bg1    = (const float*)d_in[11];
    const float* id_emb = (const float*)d_in[12];
    const float* Wp1    = (const float*)d_in[13];
    const float* bp1    = (const float*)d_in[14];
    const float* Wp2    = (const float*)d_in[15];
    const float* bp2    = (const float*)d_in[16];
    const int*   ei     = (const int*)d_in[17];
    const int*   un     = (const int*)d_in[18];
    const int*   pit    = (const int*)d_in[19];
    const int*   nit    = (const int*)d_in[20];

    float* out      = (float*)d_out;
    float* out_pos  = out;
    float* out_neg  = out + NB;
    float* rep      = out + 2 * NB;
    float* out_pred = out + 2 * NB + (size_t)NN * DX;

    cudaFuncSetAttribute(k_gemm_x,  cudaFuncAttributeMaxDynamicSharedMemorySize, 98304);
    cudaFuncSetAttribute(k_gemm_xw, cudaFuncAttributeMaxDynamicSharedMemorySize, 98304);
    cudaFuncSetAttribute(k_rep,     cudaFuncAttributeMaxDynamicSharedMemorySize, 131072);

    k_init<<<50000, 256>>>();
    k_gemm_x<<<1563, 256, 98304>>>(feat, ufeat, Wm, bm, Wu, bu);
    k_gemm_xw<<<1563, 256, 98304>>>(Wgat);
    k_deg<<<(NE + 255) / 256, 256>>>(ei);
    k_logits<<<NE / 8, 256>>>(ei);
    k_denom<<<(NE + 255) / 256, 256>>>(ei);
    k_scatter<<<NE / 8, 256>>>(ei);
    k_finalize<<<NN / 8, 256>>>(bgat);
    k_rep<<<1563, 256, 131072>>>(Wl1, bl1, Wg1, bg1, id_emb, rep);
    k_batch<<<NB / 8, 256>>>(rep, un, pit, nit, Wp1, bp1, Wp2, bp2,
                             out_pos, out_neg, out_pred);
}

// round 2
// speedup vs baseline: 1.0834x; 1.0834x over previous
#include <cuda_runtime.h>
#include <math.h>

#define NN     100000
#define NITEM  80000
#define DD     128
#define DX     64
#define NE     800000
#define NB     4096

// ---------------- device scratch ----------------
__device__ __align__(16) float g_x [(size_t)NN * DD];
__device__ __align__(16) float g_xw[(size_t)NN * DD];
__device__ __align__(16) float g_h [(size_t)NN * DD];   // gat accumulator (raw)
__device__ int   g_deg[NN];
__device__ float g_s[NN];
__device__ float g_expv[NE];

__device__ __forceinline__ float lrelu(float v) { return v > 0.f ? v : 0.01f * v; }

// ---------------- packed f32x2 helpers (Blackwell FFMA2) ----------------
__device__ __forceinline__ unsigned long long dup2(float a) {
    unsigned long long r;
    asm("mov.b64 %0, {%1, %1};" : "=l"(r) : "r"(__float_as_uint(a)));
    return r;
}
__device__ __forceinline__ void fma2(unsigned long long& d, unsigned long long a,
                                     unsigned long long b) {
    asm("fma.rn.f32x2 %0, %1, %2, %0;" : "+l"(d) : "l"(a), "l"(b));
}
__device__ __forceinline__ float lo32(unsigned long long v) {
    return __uint_as_float((unsigned)v);
}
__device__ __forceinline__ float hi32(unsigned long long v) {
    return __uint_as_float((unsigned)(v >> 32));
}

// 8x8 per-thread microtile GEMM over K=128. A stride fixed 128, B stride LDB.
template <int LDB>
__device__ __forceinline__ void mmtile(const float* __restrict__ As,
                                       const float* __restrict__ Bs,
                                       int r0, int c0, float (&out)[8][8]) {
    unsigned long long acc[8][4];
    #pragma unroll
    for (int r = 0; r < 8; r++) {
        acc[r][0] = 0ull; acc[r][1] = 0ull; acc[r][2] = 0ull; acc[r][3] = 0ull;
    }
    #pragma unroll 1
    for (int k = 0; k < 128; k += 4) {
        float4 av[8];
        #pragma unroll
        for (int r = 0; r < 8; r++)
            av[r] = *(const float4*)(As + (r0 + r) * 128 + k);
        #pragma unroll
        for (int kk = 0; kk < 4; kk++) {
            ulonglong2 b01 = *(const ulonglong2*)(Bs + (k + kk) * LDB + c0);
            ulonglong2 b23 = *(const ulonglong2*)(Bs + (k + kk) * LDB + c0 + 4);
            #pragma unroll
            for (int r = 0; r < 8; r++) {
                float a = (kk == 0) ? av[r].x : (kk == 1) ? av[r].y
                        : (kk == 2) ? av[r].z : av[r].w;
                unsigned long long ad = dup2(a);
                fma2(acc[r][0], ad, b01.x);
                fma2(acc[r][1], ad, b01.y);
                fma2(acc[r][2], ad, b23.x);
                fma2(acc[r][3], ad, b23.y);
            }
        }
    }
    #pragma unroll
    for (int r = 0; r < 8; r++) {
        out[r][0] = lo32(acc[r][0]); out[r][1] = hi32(acc[r][0]);
        out[r][2] = lo32(acc[r][1]); out[r][3] = hi32(acc[r][1]);
        out[r][4] = lo32(acc[r][2]); out[r][5] = hi32(acc[r][2]);
        out[r][6] = lo32(acc[r][3]); out[r][7] = hi32(acc[r][3]);
    }
}

// ---------------- init ----------------
__global__ void k_init() {
    int i = blockIdx.x * 256 + threadIdx.x;
    if (i < NN * DD / 4)
        ((float4*)g_h)[i] = make_float4(0.f, 0.f, 0.f, 0.f);
    if (i < NN) { g_deg[i] = 0; g_s[i] = 0.f; }
}

// ---------------- fused: x = l2norm(tanh(feat@W.T+b)); xw = x@W_gat ----------------
__global__ void __launch_bounds__(256, 1) k_gemm_fused(
    const float* __restrict__ feat, const float* __restrict__ ufeat,
    const float* __restrict__ Wm, const float* __restrict__ bm,
    const float* __restrict__ Wu, const float* __restrict__ bu,
    const float* __restrict__ Wg)
{
    extern __shared__ float smx[];
    float* As = smx;            // 128 x 128
    float* Bs = smx + 16384;    // 128 x 128
    const int row0 = blockIdx.x * 128;
    const bool user = row0 >= NITEM;
    const float* A    = user ? (ufeat + (size_t)(row0 - NITEM) * DD)
                             : (feat  + (size_t)row0 * DD);
    const float* W    = user ? Wu : Wm;
    const float* bias = user ? bu : bm;
    int rowlim = NN - row0; if (rowlim > 128) rowlim = 128;
    const int tid = threadIdx.x;

    // stage A
    for (int i = tid; i < 128 * 32; i += 256) {
        int r = i >> 5, c4 = i & 31;
        float4 v = make_float4(0.f, 0.f, 0.f, 0.f);
        if (r < rowlim) v = __ldg((const float4*)A + (size_t)r * 32 + c4);
        *(float4*)&As[r * 128 + c4 * 4] = v;
    }
    // stage Bs = W^T (first GEMM is feat @ W.T)
    for (int i = tid; i < 128 * 32; i += 256) {
        int j = i & 127, c4 = i >> 7;
        float4 v = __ldg((const float4*)W + j * 32 + c4);
        Bs[(c4 * 4 + 0) * 128 + j] = v.x;
        Bs[(c4 * 4 + 1) * 128 + j] = v.y;
        Bs[(c4 * 4 + 2) * 128 + j] = v.z;
        Bs[(c4 * 4 + 3) * 128 + j] = v.w;
    }
    __syncthreads();

    const int ty = tid >> 4, tx = tid & 15;
    const int r0 = ty * 8, c0 = tx * 8;
    float v[8][8];
    mmtile<128>(As, Bs, r0, c0, v);

    // bias + tanh + row l2norm (row spread over 16 lanes sharing ty)
    float4 bb0 = __ldg((const float4*)(bias + c0));
    float4 bb1 = __ldg((const float4*)(bias + c0 + 4));
    float bcol[8] = {bb0.x, bb0.y, bb0.z, bb0.w, bb1.x, bb1.y, bb1.z, bb1.w};
    #pragma unroll
    for (int r = 0; r < 8; r++) {
        float ss = 0.f;
        #pragma unroll
        for (int c = 0; c < 8; c++) {
            float t = tanhf(v[r][c] + bcol[c]);
            v[r][c] = t; ss += t * t;
        }
        #pragma unroll
        for (int o = 8; o; o >>= 1) ss += __shfl_xor_sync(0xffffffffu, ss, o);
        float inv = 1.f / fmaxf(sqrtf(ss), 1e-12f);
        #pragma unroll
        for (int c = 0; c < 8; c++) v[r][c] *= inv;
        int grow = row0 + r0 + r;
        if (grow < NN) {
            *(float4*)&g_x[(size_t)grow * 128 + c0] =
                make_float4(v[r][0], v[r][1], v[r][2], v[r][3]);
            *(float4*)&g_x[(size_t)grow * 128 + c0 + 4] =
                make_float4(v[r][4], v[r][5], v[r][6], v[r][7]);
        }
    }
    __syncthreads();   // all reads of As/Bs done

    // phase 2: As <- x tile, Bs <- W_gat (no transpose: xw = x @ Wg)
    #pragma unroll
    for (int r = 0; r < 8; r++) {
        *(float4*)&As[(r0 + r) * 128 + c0] =
            make_float4(v[r][0], v[r][1], v[r][2], v[r][3]);
        *(float4*)&As[(r0 + r) * 128 + c0 + 4] =
            make_float4(v[r][4], v[r][5], v[r][6], v[r][7]);
    }
    for (int i = tid; i < 128 * 32; i += 256) {
        int kk = i >> 5, c4 = i & 31;
        float4 w = __ldg((const float4*)Wg + kk * 32 + c4);
        *(float4*)&Bs[kk * 128 + c4 * 4] = w;
    }
    __syncthreads();

    mmtile<128>(As, Bs, r0, c0, v);
    #pragma unroll
    for (int r = 0; r < 8; r++) {
        int grow = row0 + r0 + r;
        if (grow < NN) {
            *(float4*)&g_xw[(size_t)grow * 128 + c0] =
                make_float4(v[r][0], v[r][1], v[r][2], v[r][3]);
            *(float4*)&g_xw[(size_t)grow * 128 + c0 + 4] =
                make_float4(v[r][4], v[r][5], v[r][6], v[r][7]);
        }
    }
}

// ---------------- out-degree of src ----------------
__global__ void k_deg(const int* __restrict__ ei) {
    int e = blockIdx.x * 256 + threadIdx.x;
    if (e < NE) atomicAdd(&g_deg[ei[e]], 1);
}

// ---------------- per-edge logits + exp + denom (max pass dropped: |logit|<=0.2) --------
__global__ void k_edge1(const int* __restrict__ ei) {
    int gt = blockIdx.x * 256 + threadIdx.x;
    int e = gt >> 5, lane = gt & 31;
    if (e >= NE) return;
    int sj = __ldg(ei + e);
    int di = __ldg(ei + NE + e);
    float4 a = *((const float4*)(g_xw + (size_t)sj * DD) + lane);
    float4 b = *((const float4*)(g_xw + (size_t)di * DD) + lane);
    float p = a.x * b.x + a.y * b.y + a.z * b.z + a.w * b.w;
    #pragma unroll
    for (int o = 16; o; o >>= 1) p += __shfl_xor_sync(0xffffffffu, p, o);
    if (lane == 0) {
        float dinv = rsqrtf((float)g_deg[sj]);
        float gate = 1.f / (1.f + __expf(-dinv * p));
        float ev = __expf(p * gate);
        g_expv[e] = ev;
        atomicAdd(&g_s[di], ev);
    }
}

// ---------------- weighted scatter: acc[dst] += att * xw[src] ----------------
__global__ void k_scatter(const int* __restrict__ ei) {
    int gt = blockIdx.x * 256 + threadIdx.x;
    int e = gt >> 5, lane = gt & 31;
    if (e >= NE) return;
    int sj = __ldg(ei + e);
    int di = __ldg(ei + NE + e);
    float att = g_expv[e] / (g_s[di] + 1e-16f);
    float4 a = *((const float4*)(g_xw + (size_t)sj * DD) + lane);
    float4 v = make_float4(a.x * att, a.y * att, a.z * att, a.w * att);
    atomicAdd((float4*)(g_h + (size_t)di * DD) + lane, v);
}

// ---------------- rep = lrelu(h@Wg1.T+bg1 + lrelu(x@Wl1.T+bl1) + id_emb) ----------------
// also folds finalize: h = lrelu(l2norm(acc + b_gat)) done in smem during staging
__global__ void __launch_bounds__(256, 1) k_rep(
    const float* __restrict__ Wl1, const float* __restrict__ bl1,
    const float* __restrict__ Wg1, const float* __restrict__ bg1,
    const float* __restrict__ bgat, const float* __restrict__ id_emb,
    float* __restrict__ rep)
{
    extern __shared__ float smx[];
    float* Xs  = smx;            // 128 x 128
    float* Hs  = smx + 16384;    // 128 x 128
    float* W1s = smx + 32768;    // 128 x 64 (transposed Wl1), later epilogue buf
    float* Wgs = smx + 40960;    // 128 x 64 (transposed Wg1)
    const int row0 = blockIdx.x * 128;
    int rowlim = NN - row0; if (rowlim > 128) rowlim = 128;
    const int tid = threadIdx.x;

    for (int i = tid; i < 128 * 32; i += 256) {
        int r = i >> 5, c4 = i & 31;
        float4 vx = make_float4(0.f, 0.f, 0.f, 0.f), vh = vx;
        if (r < rowlim) {
            vx = *((const float4*)(g_x + (size_t)(row0 + r) * 128) + c4);
            vh = *((const float4*)(g_h + (size_t)(row0 + r) * 128) + c4);
        }
        *(float4*)&Xs[r * 128 + c4 * 4] = vx;
        *(float4*)&Hs[r * 128 + c4 * 4] = vh;
    }
    for (int i = tid; i < 64 * 32; i += 256) {
        int j = i & 63, c4 = i >> 6;
        float4 v1 = __ldg((const float4*)Wl1 + j * 32 + c4);
        float4 vg = __ldg((const float4*)Wg1 + j * 32 + c4);
        W1s[(c4 * 4 + 0) * 64 + j] = v1.x; W1s[(c4 * 4 + 1) * 64 + j] = v1.y;
        W1s[(c4 * 4 + 2) * 64 + j] = v1.z; W1s[(c4 * 4 + 3) * 64 + j] = v1.w;
        Wgs[(c4 * 4 + 0) * 64 + j] = vg.x; Wgs[(c4 * 4 + 1) * 64 + j] = vg.y;
        Wgs[(c4 * 4 + 2) * 64 + j] = vg.z; Wgs[(c4 * 4 + 3) * 64 + j] = vg.w;
    }
    __syncthreads();

    // finalize h rows in smem: lrelu(l2norm(acc + bgat))
    {
        int warp = tid >> 5, lane = tid & 31;
        float4 bb = __ldg((const float4*)bgat + lane);
        #pragma unroll 1
        for (int rr = 0; rr < 16; rr++) {
            int row = warp * 16 + rr;
            float4 h = *(float4*)&Hs[row * 128 + lane * 4];
            h.x += bb.x; h.y += bb.y; h.z += bb.z; h.w += bb.w;
            float ss = h.x * h.x + h.y * h.y + h.z * h.z + h.w * h.w;
            #pragma unroll
            for (int o = 16; o; o >>= 1) ss += __shfl_xor_sync(0xffffffffu, ss, o);
            float inv = 1.f / fmaxf(sqrtf(ss), 1e-12f);
            h.x = lrelu(h.x * inv); h.y = lrelu(h.y * inv);
            h.z = lrelu(h.z * inv); h.w = lrelu(h.w * inv);
            *(float4*)&Hs[row * 128 + lane * 4] = h;
        }
    }
    __syncthreads();

    // half 0: x @ Wl1.T ; half 1: h @ Wg1.T   (each half: 128 threads, 8x8 tiles)
    const int half = tid >> 7, t = tid & 127;
    const int r0 = (t >> 3) * 8, c0 = (t & 7) * 8;
    const float* Ablk = half ? Hs : Xs;
    const float* Wblk = half ? Wgs : W1s;
    float v[8][8];
    mmtile<64>(Ablk, Wblk, r0, c0, v);
    __syncthreads();    // done reading W1s — reuse as epilogue buffer

    float* buf = W1s;   // 128 x 64
    if (half == 0) {
        float4 b0 = __ldg((const float4*)(bl1 + c0));
        float4 b1 = __ldg((const float4*)(bl1 + c0 + 4));
        float bc[8] = {b0.x, b0.y, b0.z, b0.w, b1.x, b1.y, b1.z, b1.w};
        #pragma unroll
        for (int r = 0; r < 8; r++) {
            int grow = row0 + r0 + r;
            float4 e0 = make_float4(0.f, 0.f, 0.f, 0.f), e1 = e0;
            if (grow < NN) {
                e0 = __ldg((const float4*)(id_emb + (size_t)grow * 64 + c0));
                e1 = __ldg((const float4*)(id_emb + (size_t)grow * 64 + c0 + 4));
            }
            float em[8] = {e0.x, e0.y, e0.z, e0.w, e1.x, e1.y, e1.z, e1.w};
            #pragma unroll
            for (int c = 0; c < 8; c++)
                buf[(r0 + r) * 64 + c0 + c] = lrelu(v[r][c] + bc[c]) + em[c];
        }
    }
    __syncthreads();
    if (half == 1) {
        float4 b0 = __ldg((const float4*)(bg1 + c0));
        float4 b1 = __ldg((const float4*)(bg1 + c0 + 4));
        float bc[8] = {b0.x, b0.y, b0.z, b0.w, b1.x, b1.y, b1.z, b1.w};
        #pragma unroll
        for (int r = 0; r < 8; r++) {
            int grow = row0 + r0 + r;
            if (grow < NN) {
                float o[8];
                #pragma unroll
                for (int c = 0; c < 8; c++)
                    o[c] = lrelu(v[r][c] + bc[c] + buf[(r0 + r) * 64 + c0 + c]);
                *(float4*)&rep[(size_t)grow * 64 + c0] =
                    make_float4(o[0], o[1], o[2], o[3]);
                *(float4*)&rep[(size_t)grow * 64 + c0 + 4] =
                    make_float4(o[4], o[5], o[6], o[7]);
            }
        }
    }
}

// ---------------- batch head (one warp per batch element) ----------------
__global__ void k_batch(const float* __restrict__ rep,
                        const int* __restrict__ un, const int* __restrict__ pit,
                        const int* __restrict__ nit,
                        const float* __restrict__ Wp1, const float* __restrict__ bp1,
                        const float* __restrict__ Wp2, const float* __restrict__ bp2,
                        float* __restrict__ out_pos, float* __restrict__ out_neg,
                        float* __restrict__ out_pred)
{
    int gt = blockIdx.x * 256 + threadIdx.x;
    int w = gt >> 5, lane = gt & 31;
    if (w >= NB) return;
    int iu = __ldg(un + w), ip = __ldg(pit + w), inn = __ldg(nit + w);
    float u0 = __ldg(rep + (size_t)iu * DX + lane), u1 = __ldg(rep + (size_t)iu * DX + 32 + lane);
    float p0 = __ldg(rep + (size_t)ip * DX + lane), p1 = __ldg(rep + (size_t)ip * DX + 32 + lane);
    float n0 = __ldg(rep + (size_t)inn * DX + lane), n1 = __ldg(rep + (size_t)inn * DX + 32 + lane);
    float ps = u0 * p0 + u1 * p1;
    float ns = u0 * n0 + u1 * n1;
    #pragma unroll
    for (int o = 16; o; o >>= 1) {
        ps += __shfl_xor_sync(0xffffffffu, ps, o);
        ns += __shfl_xor_sync(0xffffffffu, ns, o);
    }
    float h0 = __ldg(bp1 + lane), h1 = __ldg(bp1 + lane + 32);
    #pragma unroll 4
    for (int k = 0; k < 128; k++) {
        float srcv = (k < 32) ? u0 : (k < 64) ? u1 : (k < 96) ? p0 : p1;
        float v = __shfl_sync(0xffffffffu, srcv, k & 31);
        h0 += __ldg(Wp1 + lane * 128 + k) * v;
        h1 += __ldg(Wp1 + (lane + 32) * 128 + k) * v;
    }
    h0 = lrelu(h0); h1 = lrelu(h1);
    float pp = __ldg(Wp2 + lane) * h0 + __ldg(Wp2 + lane + 32) * h1;
    #pragma unroll
    for (int o = 16; o; o >>= 1) pp += __shfl_xor_sync(0xffffffffu, pp, o);
    if (lane == 0) {
        out_pos[w] = ps;
        out_neg[w] = ns;
        out_pred[w] = 1.f / (1.f + __expf(-(pp + __ldg(bp2))));
    }
}

// ---------------- launch ----------------
extern "C" void kernel_launch(void* const* d_in, const int* in_sizes, int n_in,
                              void* d_out, int out_size)
{
    const float* feat   = (const float*)d_in[0];
    const float* ufeat  = (const float*)d_in[1];
    const float* Wm     = (const float*)d_in[2];
    const float* bm     = (const float*)d_in[3];
    const float* Wu     = (const float*)d_in[4];
    const float* bu     = (const float*)d_in[5];
    const float* Wgat   = (const float*)d_in[6];
    const float* bgat   = (const float*)d_in[7];
    const float* Wl1    = (const float*)d_in[8];
    const float* bl1    = (const float*)d_in[9];
    const float* Wg1    = (const float*)d_in[10];
    const float* bg1    = (const float*)d_in[11];
    const float* id_emb = (const float*)d_in[12];
    const float* Wp1    = (const float*)d_in[13];
    const float* bp1    = (const float*)d_in[14];
    const float* Wp2    = (const float*)d_in[15];
    const float* bp2    = (const float*)d_in[16];
    const int*   ei     = (const int*)d_in[17];
    const int*   un     = (const int*)d_in[18];
    const int*   pit    = (const int*)d_in[19];
    const int*   nit    = (const int*)d_in[20];

    float* out      = (float*)d_out;
    float* out_pos  = out;
    float* out_neg  = out + NB;
    float* rep      = out + 2 * NB;
    float* out_pred = out + 2 * NB + (size_t)NN * DX;

    cudaFuncSetAttribute(k_gemm_fused, cudaFuncAttributeMaxDynamicSharedMemorySize, 131072);
    cudaFuncSetAttribute(k_rep,        cudaFuncAttributeMaxDynamicSharedMemorySize, 196608);

    k_init<<<12500, 256>>>();
    k_gemm_fused<<<782, 256, 131072>>>(feat, ufeat, Wm, bm, Wu, bu, Wgat);
    k_deg<<<(NE + 255) / 256, 256>>>(ei);
    k_edge1<<<NE / 8, 256>>>(ei);
    k_scatter<<<NE / 8, 256>>>(ei);
    k_rep<<<782, 256, 196608>>>(Wl1, bl1, Wg1, bg1, bgat, id_emb, rep);
    k_batch<<<NB / 8, 256>>>(rep, un, pit, nit, Wp1, bp1, Wp2, bp2,
                             out_pos, out_neg, out_pred);
}

// round 3
// speedup vs baseline: 1.1622x; 1.0727x over previous
#include <cuda_runtime.h>
#include <math.h>

#define NN     100000
#define NITEM  80000
#define DD     128
#define DX     64
#define NE     800000
#define NB     4096

// ---------------- device scratch ----------------
__device__ __align__(16) float g_x [(size_t)NN * DD];
__device__ __align__(16) float g_xw[(size_t)NN * DD];
__device__ __align__(16) float g_h [(size_t)NN * DD];   // finalized gat output
__device__ int g_deg[NN];        // out-degree of src
__device__ int g_cnt[NN];        // in-degree of dst (histogram)
__device__ int g_cur[NN];        // build cursors
__device__ int g_off[NN + 1];    // CSR offsets by dst
__device__ int g_csr_src[NE];    // src ids grouped by dst

__device__ __forceinline__ float lrelu(float v) { return v > 0.f ? v : 0.01f * v; }

// ---------------- packed f32x2 helpers (Blackwell FFMA2) ----------------
__device__ __forceinline__ unsigned long long dup2(float a) {
    unsigned long long r;
    asm("mov.b64 %0, {%1, %1};" : "=l"(r) : "r"(__float_as_uint(a)));
    return r;
}
__device__ __forceinline__ void fma2(unsigned long long& d, unsigned long long a,
                                     unsigned long long b) {
    asm("fma.rn.f32x2 %0, %1, %2, %0;" : "+l"(d) : "l"(a), "l"(b));
}
__device__ __forceinline__ float lo32(unsigned long long v) {
    return __uint_as_float((unsigned)v);
}
__device__ __forceinline__ float hi32(unsigned long long v) {
    return __uint_as_float((unsigned)(v >> 32));
}

template <int LDB>
__device__ __forceinline__ void mmtile(const float* __restrict__ As,
                                       const float* __restrict__ Bs,
                                       int r0, int c0, float (&out)[8][8]) {
    unsigned long long acc[8][4];
    #pragma unroll
    for (int r = 0; r < 8; r++) {
        acc[r][0] = 0ull; acc[r][1] = 0ull; acc[r][2] = 0ull; acc[r][3] = 0ull;
    }
    #pragma unroll 1
    for (int k = 0; k < 128; k += 4) {
        float4 av[8];
        #pragma unroll
        for (int r = 0; r < 8; r++)
            av[r] = *(const float4*)(As + (r0 + r) * 128 + k);
        #pragma unroll
        for (int kk = 0; kk < 4; kk++) {
            ulonglong2 b01 = *(const ulonglong2*)(Bs + (k + kk) * LDB + c0);
            ulonglong2 b23 = *(const ulonglong2*)(Bs + (k + kk) * LDB + c0 + 4);
            #pragma unroll
            for (int r = 0; r < 8; r++) {
                float a = (kk == 0) ? av[r].x : (kk == 1) ? av[r].y
                        : (kk == 2) ? av[r].z : av[r].w;
                unsigned long long ad = dup2(a);
                fma2(acc[r][0], ad, b01.x);
                fma2(acc[r][1], ad, b01.y);
                fma2(acc[r][2], ad, b23.x);
                fma2(acc[r][3], ad, b23.y);
            }
        }
    }
    #pragma unroll
    for (int r = 0; r < 8; r++) {
        out[r][0] = lo32(acc[r][0]); out[r][1] = hi32(acc[r][0]);
        out[r][2] = lo32(acc[r][1]); out[r][3] = hi32(acc[r][1]);
        out[r][4] = lo32(acc[r][2]); out[r][5] = hi32(acc[r][2]);
        out[r][6] = lo32(acc[r][3]); out[r][7] = hi32(acc[r][3]);
    }
}

// ---------------- zero counters ----------------
__global__ void k_zero() {
    int i = blockIdx.x * 256 + threadIdx.x;
    if (i < NN) { g_deg[i] = 0; g_cnt[i] = 0; g_cur[i] = 0; }
}

// ---------------- histogram: src out-degree + dst in-degree ----------------
__global__ void k_hist(const int* __restrict__ ei) {
    int e = blockIdx.x * 256 + threadIdx.x;
    if (e < NE) {
        atomicAdd(&g_deg[__ldg(ei + e)], 1);
        atomicAdd(&g_cnt[__ldg(ei + NE + e)], 1);
    }
}

// ---------------- exclusive scan of g_cnt -> g_off (single block) ----------------
__global__ void __launch_bounds__(1024) k_scan() {
    __shared__ int part[1024];
    const int t = threadIdx.x;
    const int per = (NN + 1023) / 1024;
    int s0 = t * per, s1 = s0 + per; if (s1 > NN) s1 = NN;
    int s = 0;
    for (int i = s0; i < s1; i++) s += g_cnt[i];
    part[t] = s;
    __syncthreads();
    #pragma unroll
    for (int off = 1; off < 1024; off <<= 1) {
        int v = (t >= off) ? part[t - off] : 0;
        __syncthreads();
        part[t] += v;
        __syncthreads();
    }
    int base = (t == 0) ? 0 : part[t - 1];
    for (int i = s0; i < s1; i++) { g_off[i] = base; base += g_cnt[i]; }
    if (t == 1023) g_off[NN] = base;
}

// ---------------- CSR build: group src ids by dst ----------------
__global__ void k_build(const int* __restrict__ ei) {
    int e = blockIdx.x * 256 + threadIdx.x;
    if (e >= NE) return;
    int sj = __ldg(ei + e);
    int di = __ldg(ei + NE + e);
    int pos = g_off[di] + atomicAdd(&g_cur[di], 1);
    g_csr_src[pos] = sj;
}

// ---------------- fused GAT aggregation: one warp per dst node ----------------
// h[d] = lrelu(l2norm( (sum_e ev_e * xw[src_e]) / (sum_e ev_e + 1e-16) + bgat ))
__global__ void __launch_bounds__(256) k_aggr(const float* __restrict__ bgat) {
    int gt = blockIdx.x * 256 + threadIdx.x;
    int w = gt >> 5, lane = gt & 31;
    if (w >= NN) return;

    float4 xd = *((const float4*)(g_xw + (size_t)w * DD) + lane);
    int p   = __ldg(&g_off[w]);
    int end = __ldg(&g_off[w + 1]);

    float4 acc = make_float4(0.f, 0.f, 0.f, 0.f);
    float s = 0.f;

    // software-pipelined: prefetch next row while reducing current
    float4 a; float dg;
    if (p < end) {
        int sj = __ldg(&g_csr_src[p]);
        a  = *((const float4*)(g_xw + (size_t)sj * DD) + lane);
        dg = (float)__ldg(&g_deg[sj]);
    }
    while (p < end) {
        float4 a_n; float dg_n;
        if (p + 1 < end) {
            int sj = __ldg(&g_csr_src[p + 1]);
            a_n  = *((const float4*)(g_xw + (size_t)sj * DD) + lane);
            dg_n = (float)__ldg(&g_deg[sj]);
        }
        float d = a.x * xd.x + a.y * xd.y + a.z * xd.z + a.w * xd.w;
        #pragma unroll
        for (int o = 16; o; o >>= 1) d += __shfl_xor_sync(0xffffffffu, d, o);
        float gate = 1.f / (1.f + __expf(-rsqrtf(dg) * d));
        float ev = __expf(d * gate);
        s += ev;
        acc.x += ev * a.x; acc.y += ev * a.y;
        acc.z += ev * a.z; acc.w += ev * a.w;
        a = a_n; dg = dg_n; p++;
    }

    float inv_s = 1.f / (s + 1e-16f);
    float4 bb = __ldg((const float4*)bgat + lane);
    float4 h = make_float4(acc.x * inv_s + bb.x, acc.y * inv_s + bb.y,
                           acc.z * inv_s + bb.z, acc.w * inv_s + bb.w);
    float ss = h.x * h.x + h.y * h.y + h.z * h.z + h.w * h.w;
    #pragma unroll
    for (int o = 16; o; o >>= 1) ss += __shfl_xor_sync(0xffffffffu, ss, o);
    float inv = 1.f / fmaxf(sqrtf(ss), 1e-12f);
    h.x = lrelu(h.x * inv); h.y = lrelu(h.y * inv);
    h.z = lrelu(h.z * inv); h.w = lrelu(h.w * inv);
    *((float4*)(g_h + (size_t)w * DD) + lane) = h;
}

// ---------------- fused: x = l2norm(tanh(feat@W.T+b)); xw = x@W_gat ----------------
__global__ void __launch_bounds__(256, 1) k_gemm_fused(
    const float* __restrict__ feat, const float* __restrict__ ufeat,
    const float* __restrict__ Wm, const float* __restrict__ bm,
    const float* __restrict__ Wu, const float* __restrict__ bu,
    const float* __restrict__ Wg)
{
    extern __shared__ float smx[];
    float* As = smx;            // 128 x 128
    float* Bs = smx + 16384;    // 128 x 128
    const int row0 = blockIdx.x * 128;
    const bool user = row0 >= NITEM;
    const float* A    = user ? (ufeat + (size_t)(row0 - NITEM) * DD)
                             : (feat  + (size_t)row0 * DD);
    const float* W    = user ? Wu : Wm;
    const float* bias = user ? bu : bm;
    int rowlim = NN - row0; if (rowlim > 128) rowlim = 128;
    const int tid = threadIdx.x;

    for (int i = tid; i < 128 * 32; i += 256) {
        int r = i >> 5, c4 = i & 31;
        float4 v = make_float4(0.f, 0.f, 0.f, 0.f);
        if (r < rowlim) v = __ldg((const float4*)A + (size_t)r * 32 + c4);
        *(float4*)&As[r * 128 + c4 * 4] = v;
    }
    for (int i = tid; i < 128 * 32; i += 256) {
        int j = i & 127, c4 = i >> 7;
        float4 v = __ldg((const float4*)W + j * 32 + c4);
        Bs[(c4 * 4 + 0) * 128 + j] = v.x;
        Bs[(c4 * 4 + 1) * 128 + j] = v.y;
        Bs[(c4 * 4 + 2) * 128 + j] = v.z;
        Bs[(c4 * 4 + 3) * 128 + j] = v.w;
    }
    __syncthreads();

    const int ty = tid >> 4, tx = tid & 15;
    const int r0 = ty * 8, c0 = tx * 8;
    float v[8][8];
    mmtile<128>(As, Bs, r0, c0, v);

    float4 bb0 = __ldg((const float4*)(bias + c0));
    float4 bb1 = __ldg((const float4*)(bias + c0 + 4));
    float bcol[8] = {bb0.x, bb0.y, bb0.z, bb0.w, bb1.x, bb1.y, bb1.z, bb1.w};
    #pragma unroll
    for (int r = 0; r < 8; r++) {
        float ss = 0.f;
        #pragma unroll
        for (int c = 0; c < 8; c++) {
            float t = tanhf(v[r][c] + bcol[c]);
            v[r][c] = t; ss += t * t;
        }
        #pragma unroll
        for (int o = 8; o; o >>= 1) ss += __shfl_xor_sync(0xffffffffu, ss, o);
        float inv = 1.f / fmaxf(sqrtf(ss), 1e-12f);
        #pragma unroll
        for (int c = 0; c < 8; c++) v[r][c] *= inv;
        int grow = row0 + r0 + r;
        if (grow < NN) {
            *(float4*)&g_x[(size_t)grow * 128 + c0] =
                make_float4(v[r][0], v[r][1], v[r][2], v[r][3]);
            *(float4*)&g_x[(size_t)grow * 128 + c0 + 4] =
                make_float4(v[r][4], v[r][5], v[r][6], v[r][7]);
        }
    }
    __syncthreads();

    #pragma unroll
    for (int r = 0; r < 8; r++) {
        *(float4*)&As[(r0 + r) * 128 + c0] =
            make_float4(v[r][0], v[r][1], v[r][2], v[r][3]);
        *(float4*)&As[(r0 + r) * 128 + c0 + 4] =
            make_float4(v[r][4], v[r][5], v[r][6], v[r][7]);
    }
    for (int i = tid; i < 128 * 32; i += 256) {
        int kk = i >> 5, c4 = i & 31;
        float4 w = __ldg((const float4*)Wg + kk * 32 + c4);
        *(float4*)&Bs[kk * 128 + c4 * 4] = w;
    }
    __syncthreads();

    mmtile<128>(As, Bs, r0, c0, v);
    #pragma unroll
    for (int r = 0; r < 8; r++) {
        int grow = row0 + r0 + r;
        if (grow < NN) {
            *(float4*)&g_xw[(size_t)grow * 128 + c0] =
                make_float4(v[r][0], v[r][1], v[r][2], v[r][3]);
            *(float4*)&g_xw[(size_t)grow * 128 + c0 + 4] =
                make_float4(v[r][4], v[r][5], v[r][6], v[r][7]);
        }
    }
}

// ---------------- rep = lrelu(h@Wg1.T+bg1 + lrelu(x@Wl1.T+bl1) + id_emb) ----------------
__global__ void __launch_bounds__(256, 1) k_rep(
    const float* __restrict__ Wl1, const float* __restrict__ bl1,
    const float* __restrict__ Wg1, const float* __restrict__ bg1,
    const float* __restrict__ id_emb, float* __restrict__ rep)
{
    extern __shared__ float smx[];
    float* Xs  = smx;            // 128 x 128
    float* Hs  = smx + 16384;    // 128 x 128
    float* W1s = smx + 32768;    // 128 x 64, later epilogue buf
    float* Wgs = smx + 40960;    // 128 x 64
    const int row0 = blockIdx.x * 128;
    int rowlim = NN - row0; if (rowlim > 128) rowlim = 128;
    const int tid = threadIdx.x;

    for (int i = tid; i < 128 * 32; i += 256) {
        int r = i >> 5, c4 = i & 31;
        float4 vx = make_float4(0.f, 0.f, 0.f, 0.f), vh = vx;
        if (r < rowlim) {
            vx = *((const float4*)(g_x + (size_t)(row0 + r) * 128) + c4);
            vh = *((const float4*)(g_h + (size_t)(row0 + r) * 128) + c4);
        }
        *(float4*)&Xs[r * 128 + c4 * 4] = vx;
        *(float4*)&Hs[r * 128 + c4 * 4] = vh;
    }
    for (int i = tid; i < 64 * 32; i += 256) {
        int j = i & 63, c4 = i >> 6;
        float4 v1 = __ldg((const float4*)Wl1 + j * 32 + c4);
        float4 vg = __ldg((const float4*)Wg1 + j * 32 + c4);
        W1s[(c4 * 4 + 0) * 64 + j] = v1.x; W1s[(c4 * 4 + 1) * 64 + j] = v1.y;
        W1s[(c4 * 4 + 2) * 64 + j] = v1.z; W1s[(c4 * 4 + 3) * 64 + j] = v1.w;
        Wgs[(c4 * 4 + 0) * 64 + j] = vg.x; Wgs[(c4 * 4 + 1) * 64 + j] = vg.y;
        Wgs[(c4 * 4 + 2) * 64 + j] = vg.z; Wgs[(c4 * 4 + 3) * 64 + j] = vg.w;
    }
    __syncthreads();

    const int half = tid >> 7, t = tid & 127;
    const int r0 = (t >> 3) * 8, c0 = (t & 7) * 8;
    const float* Ablk = half ? Hs : Xs;
    const float* Wblk = half ? Wgs : W1s;
    float v[8][8];
    mmtile<64>(Ablk, Wblk, r0, c0, v);
    __syncthreads();

    float* buf = W1s;
    if (half == 0) {
        float4 b0 = __ldg((const float4*)(bl1 + c0));
        float4 b1 = __ldg((const float4*)(bl1 + c0 + 4));
        float bc[8] = {b0.x, b0.y, b0.z, b0.w, b1.x, b1.y, b1.z, b1.w};
        #pragma unroll
        for (int r = 0; r < 8; r++) {
            int grow = row0 + r0 + r;
            float4 e0 = make_float4(0.f, 0.f, 0.f, 0.f), e1 = e0;
            if (grow < NN) {
                e0 = __ldg((const float4*)(id_emb + (size_t)grow * 64 + c0));
                e1 = __ldg((const float4*)(id_emb + (size_t)grow * 64 + c0 + 4));
            }
            float em[8] = {e0.x, e0.y, e0.z, e0.w, e1.x, e1.y, e1.z, e1.w};
            #pragma unroll
            for (int c = 0; c < 8; c++)
                buf[(r0 + r) * 64 + c0 + c] = lrelu(v[r][c] + bc[c]) + em[c];
        }
    }
    __syncthreads();
    if (half == 1) {
        float4 b0 = __ldg((const float4*)(bg1 + c0));
        float4 b1 = __ldg((const float4*)(bg1 + c0 + 4));
        float bc[8] = {b0.x, b0.y, b0.z, b0.w, b1.x, b1.y, b1.z, b1.w};
        #pragma unroll
        for (int r = 0; r < 8; r++) {
            int grow = row0 + r0 + r;
            if (grow < NN) {
                float o[8];
                #pragma unroll
                for (int c = 0; c < 8; c++)
                    o[c] = lrelu(v[r][c] + bc[c] + buf[(r0 + r) * 64 + c0 + c]);
                *(float4*)&rep[(size_t)grow * 64 + c0] =
                    make_float4(o[0], o[1], o[2], o[3]);
                *(float4*)&rep[(size_t)grow * 64 + c0 + 4] =
                    make_float4(o[4], o[5], o[6], o[7]);
            }
        }
    }
}

// ---------------- batch head ----------------
__global__ void k_batch(const float* __restrict__ rep,
                        const int* __restrict__ un, const int* __restrict__ pit,
                        const int* __restrict__ nit,
                        const float* __restrict__ Wp1, const float* __restrict__ bp1,
                        const float* __restrict__ Wp2, const float* __restrict__ bp2,
                        float* __restrict__ out_pos, float* __restrict__ out_neg,
                        float* __restrict__ out_pred)
{
    int gt = blockIdx.x * 256 + threadIdx.x;
    int w = gt >> 5, lane = gt & 31;
    if (w >= NB) return;
    int iu = __ldg(un + w), ip = __ldg(pit + w), inn = __ldg(nit + w);
    float u0 = __ldg(rep + (size_t)iu * DX + lane), u1 = __ldg(rep + (size_t)iu * DX + 32 + lane);
    float p0 = __ldg(rep + (size_t)ip * DX + lane), p1 = __ldg(rep + (size_t)ip * DX + 32 + lane);
    float n0 = __ldg(rep + (size_t)inn * DX + lane), n1 = __ldg(rep + (size_t)inn * DX + 32 + lane);
    float ps = u0 * p0 + u1 * p1;
    float ns = u0 * n0 + u1 * n1;
    #pragma unroll
    for (int o = 16; o; o >>= 1) {
        ps += __shfl_xor_sync(0xffffffffu, ps, o);
        ns += __shfl_xor_sync(0xffffffffu, ns, o);
    }
    float h0 = __ldg(bp1 + lane), h1 = __ldg(bp1 + lane + 32);
    #pragma unroll 4
    for (int k = 0; k < 128; k++) {
        float srcv = (k < 32) ? u0 : (k < 64) ? u1 : (k < 96) ? p0 : p1;
        float v = __shfl_sync(0xffffffffu, srcv, k & 31);
        h0 += __ldg(Wp1 + lane * 128 + k) * v;
        h1 += __ldg(Wp1 + (lane + 32) * 128 + k) * v;
    }
    h0 = lrelu(h0); h1 = lrelu(h1);
    float pp = __ldg(Wp2 + lane) * h0 + __ldg(Wp2 + lane + 32) * h1;
    #pragma unroll
    for (int o = 16; o; o >>= 1) pp += __shfl_xor_sync(0xffffffffu, pp, o);
    if (lane == 0) {
        out_pos[w] = ps;
        out_neg[w] = ns;
        out_pred[w] = 1.f / (1.f + __expf(-(pp + __ldg(bp2))));
    }
}

// ---------------- launch ----------------
extern "C" void kernel_launch(void* const* d_in, const int* in_sizes, int n_in,
                              void* d_out, int out_size)
{
    const float* feat   = (const float*)d_in[0];
    const float* ufeat  = (const float*)d_in[1];
    const float* Wm     = (const float*)d_in[2];
    const float* bm     = (const float*)d_in[3];
    const float* Wu     = (const float*)d_in[4];
    const float* bu     = (const float*)d_in[5];
    const float* Wgat   = (const float*)d_in[6];
    const float* bgat   = (const float*)d_in[7];
    const float* Wl1    = (const float*)d_in[8];
    const float* bl1    = (const float*)d_in[9];
    const float* Wg1    = (const float*)d_in[10];
    const float* bg1    = (const float*)d_in[11];
    const float* id_emb = (const float*)d_in[12];
    const float* Wp1    = (const float*)d_in[13];
    const float* bp1    = (const float*)d_in[14];
    const float* Wp2    = (const float*)d_in[15];
    const float* bp2    = (const float*)d_in[16];
    const int*   ei     = (const int*)d_in[17];
    const int*   un     = (const int*)d_in[18];
    const int*   pit    = (const int*)d_in[19];
    const int*   nit    = (const int*)d_in[20];

    float* out      = (float*)d_out;
    float* out_pos  = out;
    float* out_neg  = out + NB;
    float* rep      = out + 2 * NB;
    float* out_pred = out + 2 * NB + (size_t)NN * DX;

    cudaFuncSetAttribute(k_gemm_fused, cudaFuncAttributeMaxDynamicSharedMemorySize, 131072);
    cudaFuncSetAttribute(k_rep,        cudaFuncAttributeMaxDynamicSharedMemorySize, 196608);

    k_zero<<<(NN + 255) / 256, 256>>>();
    k_hist<<<(NE + 255) / 256, 256>>>(ei);
    k_scan<<<1, 1024>>>();
    k_build<<<(NE + 255) / 256, 256>>>(ei);
    k_gemm_fused<<<782, 256, 131072>>>(feat, ufeat, Wm, bm, Wu, bu, Wgat);
    k_aggr<<<(NN * 32 + 255) / 256, 256>>>(bgat);
    k_rep<<<782, 256, 196608>>>(Wl1, bl1, Wg1, bg1, id_emb, rep);
    k_batch<<<NB / 8, 256>>>(rep, un, pit, nit, Wp1, bp1, Wp2, bp2,
                             out_pos, out_neg, out_pred);
}